// round 13
// baseline (speedup 1.0000x reference)
#include <cuda_runtime.h>
#include <cstdint>

#define Bc 4
#define Lc 1024
#define Hc 8
#define Ec 64
#define BHc 32
#define PITCH 1028
#define TBUF 4352            // 64 rows * 68 floats per K/V buffer

// d_out packing (floats): V [B,L,H,E] | series [B,H,L,L] | prior [B,H,L,L] | sig [B,H,L,1]
#define OFF_SERIES 2097152
#define OFF_PRIOR  35651584
#define OFF_SIG    69206016

// scratch: p_density [B,H,L,E] (8 MB)
__device__ float g_p[BHc * Lc * Ec];

__device__ __forceinline__ void cp16(float* dst, const float* src) {
    unsigned int s = (unsigned int)__cvta_generic_to_shared(dst);
    asm volatile("cp.async.cg.shared.global [%0], [%1], 16;" :: "r"(s), "l"(src));
}
#define CP_COMMIT() asm volatile("cp.async.commit_group;")
#define CP_WAIT0()  asm volatile("cp.async.wait_group 0;")

__device__ __forceinline__ unsigned int tf32h(float x) {
    unsigned int r;
    asm("cvt.rna.tf32.f32 %0, %1;" : "=r"(r) : "f"(x));
    return r;
}

__device__ __forceinline__ void mma_tf32(float* d, const unsigned int* a, const unsigned int* b) {
    asm volatile("mma.sync.aligned.m16n8k8.row.col.f32.tf32.tf32.f32 "
                 "{%0,%1,%2,%3}, {%4,%5,%6,%7}, {%8,%9}, {%0,%1,%2,%3};"
                 : "+f"(d[0]), "+f"(d[1]), "+f"(d[2]), "+f"(d[3])
                 : "r"(a[0]), "r"(a[1]), "r"(a[2]), "r"(a[3]), "r"(b[0]), "r"(b[1]));
}

// load one 64-row x 64-col tile (rows at stride Hc*Ec=512 floats) into smem [64][68]
__device__ __forceinline__ void ld_tile(float* dst, const float* src, int tid) {
#pragma unroll
    for (int i = 0; i < 4; i++) {
        int f = tid + i * 256;
        int r = f >> 4, eq = f & 15;
        cp16(&dst[r * 68 + eq * 4], &src[(size_t)r * 512 + eq * 4]);
    }
}

// ---------------------------------------------------------------------------
// Kernel 1: sig + p_density.  256 threads = 4 rows x 64 e.
// ---------------------------------------------------------------------------
__global__ void __launch_bounds__(256) sig_p_kernel(const float* __restrict__ sigma,
                                                    const float* __restrict__ x,
                                                    float* __restrict__ out) {
    __shared__ float s_sig[4];
    int e    = threadIdx.x & 63;
    int rsub = threadIdx.x >> 6;
    int row  = blockIdx.x * 4 + rsub;
    int l    = row & (Lc - 1);
    int bh   = row >> 10;
    int b    = bh >> 3, h = bh & 7;

    if (e == 0) {
        float t = __fmul_rn(sigma[(b * Lc + l) * Hc + h], 5.0f);
        double sd = 1.0 / (1.0 + exp(-(double)t));
        float s = (float)sd;
        s = __fadd_rn(s, 1e-5f);
        float p3 = (float)exp((double)s * 1.0986122886681098);
        float sg = __fadd_rn(p3, -1.0f);
        s_sig[rsub] = sg;
        out[OFF_SIG + row] = sg;
    }
    __syncthreads();
    float sg = s_sig[rsub];

    float xv  = x[((size_t)(b * Lc + l) * Hc + h) * Ec + e];
    float xsq = __fmul_rn(xv, xv);
    float s2  = __fmul_rn(sg, sg);
    float dnm = __fadd_rn(s2, s2);
    float a   = __fdiv_rn(xsq, dnm);
    float ex  = expf(-a);
    float cf  = __fdiv_rn(0.3989422804014327f, sg);
    float pd  = __fadd_rn(__fmul_rn(cf, ex), 1e-5f);
    g_p[(size_t)row * Ec + e] = pd;
}

// ---------------------------------------------------------------------------
// Kernel 2: prior = P @ P^T via mma.sync tf32 (3xTF32 split). 8 warps,
// warp w: rows [16w,16w+16) x 128 cols (16 independent accumulator chains).
// ---------------------------------------------------------------------------
__global__ void __launch_bounds__(256) prior_kernel(float* __restrict__ out) {
    extern __shared__ float sm[];
    float* Ar = sm;             // [128][68]
    float* Bn = sm + 128 * 68;  // [128][68]

    int tid = threadIdx.x;
    int bh  = blockIdx.y;
    int bi  = blockIdx.x >> 3;
    int bj  = blockIdx.x & 7;

    const float* P = g_p + (size_t)bh * Lc * Ec;
    for (int f = tid; f < 2048; f += 256) {
        int r = f >> 4, eq = f & 15;
        *(float4*)&Ar[r * 68 + eq * 4] = *(const float4*)&P[(size_t)(bi * 128 + r) * 64 + eq * 4];
        *(float4*)&Bn[r * 68 + eq * 4] = *(const float4*)&P[(size_t)(bj * 128 + r) * 64 + eq * 4];
    }
    __syncthreads();

    int w   = tid >> 5, lane = tid & 31;
    int gid = lane >> 2, tig = lane & 3;

    float d[16][4];
#pragma unroll
    for (int n = 0; n < 16; n++) {
        d[n][0] = 0.f; d[n][1] = 0.f; d[n][2] = 0.f; d[n][3] = 0.f;
    }

    const float* Aw = &Ar[(w * 16 + gid) * 68];

    for (int kk = 0; kk < 8; kk++) {
        int kc = kk * 8 + tig;
        float ar0 = Aw[kc];
        float ar1 = Aw[8 * 68 + kc];
        float ar2 = Aw[kc + 4];
        float ar3 = Aw[8 * 68 + kc + 4];
        unsigned int ah[4], al[4];
        ah[0] = tf32h(ar0); al[0] = tf32h(ar0 - __uint_as_float(ah[0]));
        ah[1] = tf32h(ar1); al[1] = tf32h(ar1 - __uint_as_float(ah[1]));
        ah[2] = tf32h(ar2); al[2] = tf32h(ar2 - __uint_as_float(ah[2]));
        ah[3] = tf32h(ar3); al[3] = tf32h(ar3 - __uint_as_float(ah[3]));

#pragma unroll
        for (int n = 0; n < 16; n++) {
            float br0 = Bn[(n * 8 + gid) * 68 + kc];
            float br1 = Bn[(n * 8 + gid) * 68 + kc + 4];
            unsigned int bh2[2], bl2[2];
            bh2[0] = tf32h(br0); bl2[0] = tf32h(br0 - __uint_as_float(bh2[0]));
            bh2[1] = tf32h(br1); bl2[1] = tf32h(br1 - __uint_as_float(bh2[1]));

            mma_tf32(d[n], ah, bh2);
            mma_tf32(d[n], ah, bl2);
            mma_tf32(d[n], al, bh2);
        }
    }

    float* o = out + OFF_PRIOR + (size_t)bh * Lc * Lc;
    int rowg = bi * 128 + w * 16 + gid;
#pragma unroll
    for (int n = 0; n < 16; n++) {
        int col = bj * 128 + n * 8 + tig * 2;
        *(float2*)&o[(size_t)rowg * Lc + col]       = make_float2(d[n][0], d[n][1]);
        *(float2*)&o[(size_t)(rowg + 8) * Lc + col] = make_float2(d[n][2], d[n][3]);
    }
}

// ---------------------------------------------------------------------------
// Kernel 3: fused causal attention, tensor-core phases. 256 threads, 8 warps.
// 3 independent mma accumulator chains (hh/hl/lh) per phase; ONE barrier per
// tile iteration (wait0 -> sync -> prefetch -> compute).
// ---------------------------------------------------------------------------
__global__ void __launch_bounds__(256) attn_kernel(const float* __restrict__ qg,
                                                   const float* __restrict__ kg,
                                                   const float* __restrict__ vg,
                                                   float* __restrict__ out) {
    extern __shared__ float sm[];
    float*        Sp    = sm;                                 // [16][1028]
    unsigned int* Qhi   = (unsigned int*)(sm + 16 * PITCH);   // [16][68]
    unsigned int* Qlo   = Qhi + 16 * 68;                      // [16][68]
    float*        Kn    = sm + 16 * PITCH + 2 * 16 * 68;      // 2 x [64][68]
    float*        s_inv = Kn + 2 * TBUF;                      // [16]

    int tid  = threadIdx.x;
    int w    = tid >> 5, lane = tid & 31;
    int gid  = lane >> 2, tig = lane & 3;
    int rb   = 63 - blockIdx.x;      // big blocks first
    int bh   = blockIdx.y;
    int b    = bh >> 3, h = bh & 7;
    int r0   = rb * 16;
    int nt   = (rb >> 2) + 1;        // 64-wide tiles to cover s <= r0+15
    int n_s  = nt << 6;
    const float scale = 0.125f;

    const float* kbase = &kg[((size_t)(b * Lc) * Hc + h) * Ec];
    const float* vbase = &vg[((size_t)(b * Lc) * Hc + h) * Ec];

    // load Q rows r0..r0+15, split hi/lo once (one float4 per thread)
    {
        int r = tid >> 4, eq = tid & 15;
        float4 q4 = *(const float4*)&qg[((size_t)(b * Lc + r0 + r) * Hc + h) * Ec + eq * 4];
        unsigned int h0 = tf32h(q4.x), h1 = tf32h(q4.y), h2 = tf32h(q4.z), h3 = tf32h(q4.w);
        Qhi[r * 68 + eq * 4 + 0] = h0;  Qlo[r * 68 + eq * 4 + 0] = tf32h(q4.x - __uint_as_float(h0));
        Qhi[r * 68 + eq * 4 + 1] = h1;  Qlo[r * 68 + eq * 4 + 1] = tf32h(q4.y - __uint_as_float(h1));
        Qhi[r * 68 + eq * 4 + 2] = h2;  Qlo[r * 68 + eq * 4 + 2] = tf32h(q4.z - __uint_as_float(h2));
        Qhi[r * 68 + eq * 4 + 3] = h3;  Qlo[r * 68 + eq * 4 + 3] = tf32h(q4.w - __uint_as_float(h3));
    }

    // ---- Phase 1: scores via mma -> panel (one barrier per tile)
    ld_tile(Kn, kbase, tid); CP_COMMIT();
    for (int t = 0; t < nt; t++) {
        CP_WAIT0();                  // tile t resident
        __syncthreads();             // all warps done with buffer (t+1)&1; data visible
        if (t + 1 < nt) {
            ld_tile(Kn + ((t + 1) & 1) * TBUF, kbase + (size_t)((t + 1) << 6) * 512, tid);
            CP_COMMIT();
        }
        const float* KT = Kn + (t & 1) * TBUF;
        int s0 = t << 6;

        float dhh[4] = {0.f, 0.f, 0.f, 0.f};
        float dhl[4] = {0.f, 0.f, 0.f, 0.f};
        float dlh[4] = {0.f, 0.f, 0.f, 0.f};
#pragma unroll
        for (int kk = 0; kk < 8; kk++) {
            int kc = kk * 8 + tig;
            unsigned int ah[4], al[4];
            ah[0] = Qhi[gid * 68 + kc];       al[0] = Qlo[gid * 68 + kc];
            ah[1] = Qhi[(gid + 8) * 68 + kc]; al[1] = Qlo[(gid + 8) * 68 + kc];
            ah[2] = Qhi[gid * 68 + kc + 4];       al[2] = Qlo[gid * 68 + kc + 4];
            ah[3] = Qhi[(gid + 8) * 68 + kc + 4]; al[3] = Qlo[(gid + 8) * 68 + kc + 4];

            float br0 = KT[(w * 8 + gid) * 68 + kc];
            float br1 = KT[(w * 8 + gid) * 68 + kc + 4];
            unsigned int bh2[2], bl2[2];
            bh2[0] = tf32h(br0); bl2[0] = tf32h(br0 - __uint_as_float(bh2[0]));
            bh2[1] = tf32h(br1); bl2[1] = tf32h(br1 - __uint_as_float(bh2[1]));

            mma_tf32(dhh, ah, bh2);   // 3 independent chains
            mma_tf32(dhl, ah, bl2);
            mma_tf32(dlh, al, bh2);
        }
        float d0 = dhh[0] + (dhl[0] + dlh[0]);
        float d1 = dhh[1] + (dhl[1] + dlh[1]);
        float d2 = dhh[2] + (dhl[2] + dlh[2]);
        float d3v = dhh[3] + (dhl[3] + dlh[3]);

        int sb = s0 + w * 8 + tig * 2;
        int l0 = r0 + gid, l1 = r0 + gid + 8;
        float m0 = (sb     <= l0) ? d0 * scale : -3.4e38f;
        float m1 = (sb + 1 <= l0) ? d1 * scale : -3.4e38f;
        float m2 = (sb     <= l1) ? d2 * scale : -3.4e38f;
        float m3 = (sb + 1 <= l1) ? d3v * scale : -3.4e38f;
        *(float2*)&Sp[gid * PITCH + sb]       = make_float2(m0, m1);
        *(float2*)&Sp[(gid + 8) * PITCH + sb] = make_float2(m2, m3);
    }
    __syncthreads();                 // panel complete before softmax

    // ---- Phase 2: softmax (warp w rows 2w,2w+1). Panel keeps UNNORMALIZED exp;
    //      inv -> s_inv; series = exp*inv straight to gmem.
    for (int rr = 0; rr < 2; rr++) {
        int r = w * 2 + rr;
        float* rowp = &Sp[r * PITCH];

        float m = -3.4e38f;
        for (int s4 = lane * 4; s4 < n_s; s4 += 128) {
            float4 v = *(float4*)&rowp[s4];
            m = fmaxf(m, fmaxf(fmaxf(v.x, v.y), fmaxf(v.z, v.w)));
        }
#pragma unroll
        for (int o = 16; o > 0; o >>= 1) m = fmaxf(m, __shfl_xor_sync(0xffffffffu, m, o));

        float sum = 0.0f;
        for (int s4 = lane * 4; s4 < n_s; s4 += 128) {
            float4 v = *(float4*)&rowp[s4];
            v.x = expf(v.x - m); v.y = expf(v.y - m);
            v.z = expf(v.z - m); v.w = expf(v.w - m);
            *(float4*)&rowp[s4] = v;
            sum += (v.x + v.y) + (v.z + v.w);
        }
#pragma unroll
        for (int o = 16; o > 0; o >>= 1) sum += __shfl_xor_sync(0xffffffffu, sum, o);

        float inv = 1.0f / sum;
        if (lane == 0) s_inv[r] = inv;

        float* g = out + OFF_SERIES + ((size_t)bh * Lc + (r0 + r)) * Lc;
        for (int s4 = lane * 4; s4 < n_s; s4 += 128) {
            float4 v = *(float4*)&rowp[s4];
            v.x *= inv; v.y *= inv; v.z *= inv; v.w *= inv;
            *(float4*)&g[s4] = v;
        }
        for (int s4 = n_s + lane * 4; s4 < Lc; s4 += 128)
            *(float4*)&g[s4] = make_float4(0.f, 0.f, 0.f, 0.f);
    }
    __syncthreads();

    // ---- Phase 3: V = exp-panel @ values via mma; warp w -> e-cols [8w,8w+8)
    float phh[4] = {0.f, 0.f, 0.f, 0.f};
    float phl[4] = {0.f, 0.f, 0.f, 0.f};
    float plh[4] = {0.f, 0.f, 0.f, 0.f};

    ld_tile(Kn, vbase, tid); CP_COMMIT();
    for (int t = 0; t < nt; t++) {
        CP_WAIT0();
        __syncthreads();
        if (t + 1 < nt) {
            ld_tile(Kn + ((t + 1) & 1) * TBUF, vbase + (size_t)((t + 1) << 6) * 512, tid);
            CP_COMMIT();
        }
        const float* VT = Kn + (t & 1) * TBUF;
        int s0 = t << 6;

#pragma unroll
        for (int kk = 0; kk < 8; kk++) {
            int kc = kk * 8 + tig;
            float ar0 = Sp[gid * PITCH + s0 + kc];
            float ar1 = Sp[(gid + 8) * PITCH + s0 + kc];
            float ar2 = Sp[gid * PITCH + s0 + kc + 4];
            float ar3 = Sp[(gid + 8) * PITCH + s0 + kc + 4];
            unsigned int ah[4], al[4];
            ah[0] = tf32h(ar0); al[0] = tf32h(ar0 - __uint_as_float(ah[0]));
            ah[1] = tf32h(ar1); al[1] = tf32h(ar1 - __uint_as_float(ah[1]));
            ah[2] = tf32h(ar2); al[2] = tf32h(ar2 - __uint_as_float(ah[2]));
            ah[3] = tf32h(ar3); al[3] = tf32h(ar3 - __uint_as_float(ah[3]));

            float br0 = VT[(kk * 8 + tig) * 68 + w * 8 + gid];
            float br1 = VT[(kk * 8 + tig + 4) * 68 + w * 8 + gid];
            unsigned int bh2[2], bl2[2];
            bh2[0] = tf32h(br0); bl2[0] = tf32h(br0 - __uint_as_float(bh2[0]));
            bh2[1] = tf32h(br1); bl2[1] = tf32h(br1 - __uint_as_float(bh2[1]));

            mma_tf32(phh, ah, bh2);
            mma_tf32(phl, ah, bl2);
            mma_tf32(plh, al, bh2);
        }
    }

    {
        float inv0 = s_inv[gid], inv1 = s_inv[gid + 8];
        int e0 = w * 8 + tig * 2;
        float o0 = phh[0] + (phl[0] + plh[0]);
        float o1 = phh[1] + (phl[1] + plh[1]);
        float o2 = phh[2] + (phl[2] + plh[2]);
        float o3 = phh[3] + (phl[3] + plh[3]);
        *(float2*)&out[((size_t)(b * Lc + r0 + gid) * Hc + h) * Ec + e0] =
            make_float2(o0 * inv0, o1 * inv0);
        *(float2*)&out[((size_t)(b * Lc + r0 + gid + 8) * Hc + h) * Ec + e0] =
            make_float2(o2 * inv1, o3 * inv1);
    }
}

// ---------------------------------------------------------------------------
extern "C" void kernel_launch(void* const* d_in, const int* in_sizes, int n_in,
                              void* d_out, int out_size) {
    const float* q     = (const float*)d_in[0];
    const float* k     = (const float*)d_in[1];
    const float* v     = (const float*)d_in[2];
    const float* sigma = (const float*)d_in[3];
    const float* x     = (const float*)d_in[4];
    float* out = (float*)d_out;

    const int SMEM_PRIOR = 2 * 128 * 68 * 4;                                   // 69,632 B
    const int SMEM_ATTN  = (16 * PITCH + 2 * 16 * 68 + 2 * TBUF + 16) * 4;     // 109,376 B -> 2 CTAs/SM

    static cudaStream_t s_side = nullptr;
    static cudaEvent_t ev_fork = nullptr, ev_join = nullptr;
    if (s_side == nullptr) {
        cudaStreamCreateWithFlags(&s_side, cudaStreamNonBlocking);
        cudaEventCreateWithFlags(&ev_fork, cudaEventDisableTiming);
        cudaEventCreateWithFlags(&ev_join, cudaEventDisableTiming);
        cudaFuncSetAttribute(prior_kernel, cudaFuncAttributeMaxDynamicSharedMemorySize, SMEM_PRIOR);
        cudaFuncSetAttribute(attn_kernel,  cudaFuncAttributeMaxDynamicSharedMemorySize, SMEM_ATTN);
    }

    cudaEventRecord(ev_fork, 0);
    cudaStreamWaitEvent(s_side, ev_fork, 0);

    sig_p_kernel<<<BHc * Lc / 4, 256, 0, s_side>>>(sigma, x, out);
    prior_kernel<<<dim3(64, BHc), 256, SMEM_PRIOR, s_side>>>(out);

    attn_kernel<<<dim3(64, BHc), 256, SMEM_ATTN>>>(q, k, v, out);

    cudaEventRecord(ev_join, s_side);
    cudaStreamWaitEvent(0, ev_join, 0);
}

// round 15
// speedup vs baseline: 1.1568x; 1.1568x over previous
#include <cuda_runtime.h>
#include <cstdint>

#define Bc 4
#define Lc 1024
#define Hc 8
#define Ec 64
#define BHc 32
#define PITCH 1028
#define TBUF 4608            // V buffer: 64 rows * 72 floats (K tiles use pitch 68 inside)

// d_out packing (floats): V [B,L,H,E] | series [B,H,L,L] | prior [B,H,L,L] | sig [B,H,L,1]
#define OFF_SERIES 2097152
#define OFF_PRIOR  35651584
#define OFF_SIG    69206016

// scratch: p_density [B,H,L,E] (8 MB)
__device__ float g_p[BHc * Lc * Ec];

__device__ __forceinline__ void cp16(float* dst, const float* src) {
    unsigned int s = (unsigned int)__cvta_generic_to_shared(dst);
    asm volatile("cp.async.cg.shared.global [%0], [%1], 16;" :: "r"(s), "l"(src));
}
#define CP_COMMIT() asm volatile("cp.async.commit_group;")
#define CP_WAIT0()  asm volatile("cp.async.wait_group 0;")

__device__ __forceinline__ unsigned int tf32h(float x) {
    unsigned int r;
    asm("cvt.rna.tf32.f32 %0, %1;" : "=r"(r) : "f"(x));
    return r;
}

__device__ __forceinline__ void mma_tf32(float* d, const unsigned int* a, const unsigned int* b) {
    asm volatile("mma.sync.aligned.m16n8k8.row.col.f32.tf32.tf32.f32 "
                 "{%0,%1,%2,%3}, {%4,%5,%6,%7}, {%8,%9}, {%0,%1,%2,%3};"
                 : "+f"(d[0]), "+f"(d[1]), "+f"(d[2]), "+f"(d[3])
                 : "r"(a[0]), "r"(a[1]), "r"(a[2]), "r"(a[3]), "r"(b[0]), "r"(b[1]));
}

// load one 64-row x 64-col tile (rows at stride 512 floats) into smem [64][pitch]
__device__ __forceinline__ void ld_tile(float* dst, const float* src, int tid, int pitch) {
#pragma unroll
    for (int i = 0; i < 4; i++) {
        int f = tid + i * 256;
        int r = f >> 4, eq = f & 15;
        cp16(&dst[r * pitch + eq * 4], &src[(size_t)r * 512 + eq * 4]);
    }
}

// ---------------------------------------------------------------------------
// Kernel 1: sig + p_density.  256 threads = 4 rows x 64 e.
// ---------------------------------------------------------------------------
__global__ void __launch_bounds__(256) sig_p_kernel(const float* __restrict__ sigma,
                                                    const float* __restrict__ x,
                                                    float* __restrict__ out) {
    __shared__ float s_sig[4];
    int e    = threadIdx.x & 63;
    int rsub = threadIdx.x >> 6;
    int row  = blockIdx.x * 4 + rsub;
    int l    = row & (Lc - 1);
    int bh   = row >> 10;
    int b    = bh >> 3, h = bh & 7;

    if (e == 0) {
        float t = __fmul_rn(sigma[(b * Lc + l) * Hc + h], 5.0f);
        double sd = 1.0 / (1.0 + exp(-(double)t));
        float s = (float)sd;
        s = __fadd_rn(s, 1e-5f);
        float p3 = (float)exp((double)s * 1.0986122886681098);
        float sg = __fadd_rn(p3, -1.0f);
        s_sig[rsub] = sg;
        out[OFF_SIG + row] = sg;
    }
    __syncthreads();
    float sg = s_sig[rsub];

    float xv  = x[((size_t)(b * Lc + l) * Hc + h) * Ec + e];
    float xsq = __fmul_rn(xv, xv);
    float s2  = __fmul_rn(sg, sg);
    float dnm = __fadd_rn(s2, s2);
    float a   = __fdiv_rn(xsq, dnm);
    float ex  = expf(-a);
    float cf  = __fdiv_rn(0.3989422804014327f, sg);
    float pd  = __fadd_rn(__fmul_rn(cf, ex), 1e-5f);
    g_p[(size_t)row * Ec + e] = pd;
}

// ---------------------------------------------------------------------------
// Kernel 2: prior = P @ P^T via mma.sync tf32 (3xTF32 split). 8 warps.
// ---------------------------------------------------------------------------
__global__ void __launch_bounds__(256) prior_kernel(float* __restrict__ out) {
    extern __shared__ float sm[];
    float* Ar = sm;             // [128][68]
    float* Bn = sm + 128 * 68;  // [128][68]

    int tid = threadIdx.x;
    int bh  = blockIdx.y;
    int bi  = blockIdx.x >> 3;
    int bj  = blockIdx.x & 7;

    const float* P = g_p + (size_t)bh * Lc * Ec;
    for (int f = tid; f < 2048; f += 256) {
        int r = f >> 4, eq = f & 15;
        *(float4*)&Ar[r * 68 + eq * 4] = *(const float4*)&P[(size_t)(bi * 128 + r) * 64 + eq * 4];
        *(float4*)&Bn[r * 68 + eq * 4] = *(const float4*)&P[(size_t)(bj * 128 + r) * 64 + eq * 4];
    }
    __syncthreads();

    int w   = tid >> 5, lane = tid & 31;
    int gid = lane >> 2, tig = lane & 3;

    float d[16][4];
#pragma unroll
    for (int n = 0; n < 16; n++) {
        d[n][0] = 0.f; d[n][1] = 0.f; d[n][2] = 0.f; d[n][3] = 0.f;
    }

    const float* Aw = &Ar[(w * 16 + gid) * 68];

    for (int kk = 0; kk < 8; kk++) {
        int kc = kk * 8 + tig;
        float ar0 = Aw[kc];
        float ar1 = Aw[8 * 68 + kc];
        float ar2 = Aw[kc + 4];
        float ar3 = Aw[8 * 68 + kc + 4];
        unsigned int ah[4], al[4];
        ah[0] = tf32h(ar0); al[0] = tf32h(ar0 - __uint_as_float(ah[0]));
        ah[1] = tf32h(ar1); al[1] = tf32h(ar1 - __uint_as_float(ah[1]));
        ah[2] = tf32h(ar2); al[2] = tf32h(ar2 - __uint_as_float(ah[2]));
        ah[3] = tf32h(ar3); al[3] = tf32h(ar3 - __uint_as_float(ah[3]));

#pragma unroll
        for (int n = 0; n < 16; n++) {
            float br0 = Bn[(n * 8 + gid) * 68 + kc];
            float br1 = Bn[(n * 8 + gid) * 68 + kc + 4];
            unsigned int bh2[2], bl2[2];
            bh2[0] = tf32h(br0); bl2[0] = tf32h(br0 - __uint_as_float(bh2[0]));
            bh2[1] = tf32h(br1); bl2[1] = tf32h(br1 - __uint_as_float(bh2[1]));

            mma_tf32(d[n], ah, bh2);
            mma_tf32(d[n], ah, bl2);
            mma_tf32(d[n], al, bh2);
        }
    }

    float* o = out + OFF_PRIOR + (size_t)bh * Lc * Lc;
    int rowg = bi * 128 + w * 16 + gid;
#pragma unroll
    for (int n = 0; n < 16; n++) {
        int col = bj * 128 + n * 8 + tig * 2;
        *(float2*)&o[(size_t)rowg * Lc + col]       = make_float2(d[n][0], d[n][1]);
        *(float2*)&o[(size_t)(rowg + 8) * Lc + col] = make_float2(d[n][2], d[n][3]);
    }
}

// ---------------------------------------------------------------------------
// Kernel 3: fused causal attention. 256 threads, 8 warps, 2 CTAs/SM.
// Phase 1: Q fragments hoisted to registers (tile-invariant) -> 16 LDS/tile.
// Phase 3: k-split across warps (warp w = k-slice w), d[8][4] persistent
// accumulators over all e-blocks, one smem reduction at the end.
// ---------------------------------------------------------------------------
__global__ void __launch_bounds__(256, 2) attn_kernel(const float* __restrict__ qg,
                                                      const float* __restrict__ kg,
                                                      const float* __restrict__ vg,
                                                      float* __restrict__ out) {
    extern __shared__ float sm[];
    float*        Sp    = sm;                                 // [16][1028]
    unsigned int* Qhi   = (unsigned int*)(sm + 16 * PITCH);   // [16][68]
    unsigned int* Qlo   = Qhi + 16 * 68;                      // [16][68]
    float*        Kn    = sm + 16 * PITCH + 2 * 16 * 68;      // 2 x TBUF (K pitch 68 / V pitch 72)
    float*        s_inv = Kn + 2 * TBUF;                      // [16]

    int tid  = threadIdx.x;
    int w    = tid >> 5, lane = tid & 31;
    int gid  = lane >> 2, tig = lane & 3;
    int rb   = 63 - blockIdx.x;      // big blocks first
    int bh   = blockIdx.y;
    int b    = bh >> 3, h = bh & 7;
    int r0   = rb * 16;
    int nt   = (rb >> 2) + 1;        // 64-wide tiles to cover s <= r0+15
    int n_s  = nt << 6;
    const float scale = 0.125f;

    const float* kbase = &kg[((size_t)(b * Lc) * Hc + h) * Ec];
    const float* vbase = &vg[((size_t)(b * Lc) * Hc + h) * Ec];

    // stage Q rows r0..r0+15 hi/lo into smem (one float4 per thread)
    {
        int r = tid >> 4, eq = tid & 15;
        float4 q4 = *(const float4*)&qg[((size_t)(b * Lc + r0 + r) * Hc + h) * Ec + eq * 4];
        unsigned int h0 = tf32h(q4.x), h1 = tf32h(q4.y), h2 = tf32h(q4.z), h3 = tf32h(q4.w);
        Qhi[r * 68 + eq * 4 + 0] = h0;  Qlo[r * 68 + eq * 4 + 0] = tf32h(q4.x - __uint_as_float(h0));
        Qhi[r * 68 + eq * 4 + 1] = h1;  Qlo[r * 68 + eq * 4 + 1] = tf32h(q4.y - __uint_as_float(h1));
        Qhi[r * 68 + eq * 4 + 2] = h2;  Qlo[r * 68 + eq * 4 + 2] = tf32h(q4.z - __uint_as_float(h2));
        Qhi[r * 68 + eq * 4 + 3] = h3;  Qlo[r * 68 + eq * 4 + 3] = tf32h(q4.w - __uint_as_float(h3));
    }
    ld_tile(Kn, kbase, tid, 68); CP_COMMIT();
    __syncthreads();                 // Q staging visible

    // hoist Q fragments to registers: [kk][frag], kk fully unrolled everywhere
    unsigned int qh[32], ql[32];
#pragma unroll
    for (int kk = 0; kk < 8; kk++) {
        int kc = kk * 8 + tig;
        qh[kk * 4 + 0] = Qhi[gid * 68 + kc];           ql[kk * 4 + 0] = Qlo[gid * 68 + kc];
        qh[kk * 4 + 1] = Qhi[(gid + 8) * 68 + kc];     ql[kk * 4 + 1] = Qlo[(gid + 8) * 68 + kc];
        qh[kk * 4 + 2] = Qhi[gid * 68 + kc + 4];       ql[kk * 4 + 2] = Qlo[gid * 68 + kc + 4];
        qh[kk * 4 + 3] = Qhi[(gid + 8) * 68 + kc + 4]; ql[kk * 4 + 3] = Qlo[(gid + 8) * 68 + kc + 4];
    }

    // ---- Phase 1: scores via mma -> panel (one barrier per tile)
    for (int t = 0; t < nt; t++) {
        CP_WAIT0();
        __syncthreads();
        if (t + 1 < nt) {
            ld_tile(Kn + ((t + 1) & 1) * TBUF, kbase + (size_t)((t + 1) << 6) * 512, tid, 68);
            CP_COMMIT();
        }
        const float* KT = Kn + (t & 1) * TBUF;
        int s0 = t << 6;

        float dhh[4] = {0.f, 0.f, 0.f, 0.f};
        float dhl[4] = {0.f, 0.f, 0.f, 0.f};
        float dlh[4] = {0.f, 0.f, 0.f, 0.f};
#pragma unroll
        for (int kk = 0; kk < 8; kk++) {
            int kc = kk * 8 + tig;
            float br0 = KT[(w * 8 + gid) * 68 + kc];
            float br1 = KT[(w * 8 + gid) * 68 + kc + 4];
            unsigned int bh2[2], bl2[2];
            bh2[0] = tf32h(br0); bl2[0] = tf32h(br0 - __uint_as_float(bh2[0]));
            bh2[1] = tf32h(br1); bl2[1] = tf32h(br1 - __uint_as_float(bh2[1]));

            mma_tf32(dhh, &qh[kk * 4], bh2);
            mma_tf32(dhl, &qh[kk * 4], bl2);
            mma_tf32(dlh, &ql[kk * 4], bh2);
        }
        float d0 = dhh[0] + (dhl[0] + dlh[0]);
        float d1 = dhh[1] + (dhl[1] + dlh[1]);
        float d2 = dhh[2] + (dhl[2] + dlh[2]);
        float d3v = dhh[3] + (dhl[3] + dlh[3]);

        int sb = s0 + w * 8 + tig * 2;
        int l0 = r0 + gid, l1 = r0 + gid + 8;
        float m0 = (sb     <= l0) ? d0 * scale : -3.4e38f;
        float m1 = (sb + 1 <= l0) ? d1 * scale : -3.4e38f;
        float m2 = (sb     <= l1) ? d2 * scale : -3.4e38f;
        float m3 = (sb + 1 <= l1) ? d3v * scale : -3.4e38f;
        *(float2*)&Sp[gid * PITCH + sb]       = make_float2(m0, m1);
        *(float2*)&Sp[(gid + 8) * PITCH + sb] = make_float2(m2, m3);
    }
    __syncthreads();                 // panel complete before softmax

    // ---- Phase 2: softmax (warp w rows 2w,2w+1); panel keeps UNNORMALIZED exp.
    for (int rr = 0; rr < 2; rr++) {
        int r = w * 2 + rr;
        float* rowp = &Sp[r * PITCH];

        float m = -3.4e38f;
        for (int s4 = lane * 4; s4 < n_s; s4 += 128) {
            float4 v = *(float4*)&rowp[s4];
            m = fmaxf(m, fmaxf(fmaxf(v.x, v.y), fmaxf(v.z, v.w)));
        }
#pragma unroll
        for (int o = 16; o > 0; o >>= 1) m = fmaxf(m, __shfl_xor_sync(0xffffffffu, m, o));

        float sum = 0.0f;
        for (int s4 = lane * 4; s4 < n_s; s4 += 128) {
            float4 v = *(float4*)&rowp[s4];
            v.x = expf(v.x - m); v.y = expf(v.y - m);
            v.z = expf(v.z - m); v.w = expf(v.w - m);
            *(float4*)&rowp[s4] = v;
            sum += (v.x + v.y) + (v.z + v.w);
        }
#pragma unroll
        for (int o = 16; o > 0; o >>= 1) sum += __shfl_xor_sync(0xffffffffu, sum, o);

        float inv = 1.0f / sum;
        if (lane == 0) s_inv[r] = inv;

        float* g = out + OFF_SERIES + ((size_t)bh * Lc + (r0 + r)) * Lc;
        for (int s4 = lane * 4; s4 < n_s; s4 += 128) {
            float4 v = *(float4*)&rowp[s4];
            v.x *= inv; v.y *= inv; v.z *= inv; v.w *= inv;
            *(float4*)&g[s4] = v;
        }
        for (int s4 = n_s + lane * 4; s4 < Lc; s4 += 128)
            *(float4*)&g[s4] = make_float4(0.f, 0.f, 0.f, 0.f);
    }
    __syncthreads();

    // ---- Phase 3: V = exp-panel @ values, k-split across warps.
    // Warp w handles k-slice [w*8, w*8+8) of every tile, all 8 e-blocks.
    float d3[8][4];
#pragma unroll
    for (int n = 0; n < 8; n++) { d3[n][0] = 0.f; d3[n][1] = 0.f; d3[n][2] = 0.f; d3[n][3] = 0.f; }

    int kc3 = w * 8 + tig;           // this warp's k columns (and +4)
    ld_tile(Kn, vbase, tid, 72); CP_COMMIT();
    for (int t = 0; t < nt; t++) {
        CP_WAIT0();
        __syncthreads();
        if (t + 1 < nt) {
            ld_tile(Kn + ((t + 1) & 1) * TBUF, vbase + (size_t)((t + 1) << 6) * 512, tid, 72);
            CP_COMMIT();
        }
        const float* VT = Kn + (t & 1) * TBUF;
        int s0 = t << 6;

        // A fragments: panel rows, this warp's k-slice (broadcast across tig groups)
        float ar0 = Sp[gid * PITCH + s0 + kc3];
        float ar1 = Sp[(gid + 8) * PITCH + s0 + kc3];
        float ar2 = Sp[gid * PITCH + s0 + kc3 + 4];
        float ar3 = Sp[(gid + 8) * PITCH + s0 + kc3 + 4];
        unsigned int ah[4], al[4];
        ah[0] = tf32h(ar0); al[0] = tf32h(ar0 - __uint_as_float(ah[0]));
        ah[1] = tf32h(ar1); al[1] = tf32h(ar1 - __uint_as_float(ah[1]));
        ah[2] = tf32h(ar2); al[2] = tf32h(ar2 - __uint_as_float(ah[2]));
        ah[3] = tf32h(ar3); al[3] = tf32h(ar3 - __uint_as_float(ah[3]));

#pragma unroll
        for (int n = 0; n < 8; n++) {
            float br0 = VT[(w * 8 + tig) * 72 + n * 8 + gid];       // pitch 72: conflict-free
            float br1 = VT[(w * 8 + tig + 4) * 72 + n * 8 + gid];
            unsigned int bh2[2], bl2[2];
            bh2[0] = tf32h(br0); bl2[0] = tf32h(br0 - __uint_as_float(bh2[0]));
            bh2[1] = tf32h(br1); bl2[1] = tf32h(br1 - __uint_as_float(bh2[1]));

            mma_tf32(d3[n], ah, bh2);   // serial into same acc; 8 independent n
            mma_tf32(d3[n], ah, bl2);
            mma_tf32(d3[n], al, bh2);
        }
    }

    // cross-warp k-reduction via smem (reuse Kn region: 8*16*64 = 8192 floats)
    __syncthreads();                 // all tiles consumed; Kn free
    float* red = Kn;
#pragma unroll
    for (int n = 0; n < 8; n++) {
        *(float2*)&red[w * 1024 + gid * 64 + n * 8 + tig * 2]       = make_float2(d3[n][0], d3[n][1]);
        *(float2*)&red[w * 1024 + (gid + 8) * 64 + n * 8 + tig * 2] = make_float2(d3[n][2], d3[n][3]);
    }
    __syncthreads();
    {
        int r  = tid >> 4;           // 0..15
        int e4 = (tid & 15) * 4;     // 0..60
        float4 s = make_float4(0.f, 0.f, 0.f, 0.f);
#pragma unroll
        for (int ww = 0; ww < 8; ww++) {
            float4 v = *(float4*)&red[ww * 1024 + r * 64 + e4];
            s.x += v.x; s.y += v.y; s.z += v.z; s.w += v.w;
        }
        float inv = s_inv[r];
        *(float4*)&out[((size_t)(b * Lc + r0 + r) * Hc + h) * Ec + e4] =
            make_float4(s.x * inv, s.y * inv, s.z * inv, s.w * inv);
    }
}

// ---------------------------------------------------------------------------
extern "C" void kernel_launch(void* const* d_in, const int* in_sizes, int n_in,
                              void* d_out, int out_size) {
    const float* q     = (const float*)d_in[0];
    const float* k     = (const float*)d_in[1];
    const float* v     = (const float*)d_in[2];
    const float* sigma = (const float*)d_in[3];
    const float* x     = (const float*)d_in[4];
    float* out = (float*)d_out;

    const int SMEM_PRIOR = 2 * 128 * 68 * 4;                                   // 69,632 B
    const int SMEM_ATTN  = (16 * PITCH + 2 * 16 * 68 + 2 * TBUF + 16) * 4;     // 111,424 B -> 2 CTAs/SM

    static cudaStream_t s_side = nullptr;
    static cudaEvent_t ev_fork = nullptr, ev_join = nullptr;
    if (s_side == nullptr) {
        cudaStreamCreateWithFlags(&s_side, cudaStreamNonBlocking);
        cudaEventCreateWithFlags(&ev_fork, cudaEventDisableTiming);
        cudaEventCreateWithFlags(&ev_join, cudaEventDisableTiming);
        cudaFuncSetAttribute(prior_kernel, cudaFuncAttributeMaxDynamicSharedMemorySize, SMEM_PRIOR);
        cudaFuncSetAttribute(attn_kernel,  cudaFuncAttributeMaxDynamicSharedMemorySize, SMEM_ATTN);
    }

    cudaEventRecord(ev_fork, 0);
    cudaStreamWaitEvent(s_side, ev_fork, 0);

    sig_p_kernel<<<BHc * Lc / 4, 256, 0, s_side>>>(sigma, x, out);
    prior_kernel<<<dim3(64, BHc), 256, SMEM_PRIOR, s_side>>>(out);

    attn_kernel<<<dim3(64, BHc), 256, SMEM_ATTN>>>(q, k, v, out);

    cudaEventRecord(ev_join, s_side);
    cudaStreamWaitEvent(0, ev_join, 0);
}